// round 5
// baseline (speedup 1.0000x reference)
#include <cuda_runtime.h>
#include <cuda_fp16.h>
#include <cstdint>
#include <math.h>

// ---------------------------------------------------------------------------
// GAT 4-layer stack on GB300, round 5:
//  - fp16 mma.sync m16n8k16 GEMM, fp32 accum, cp.async double-buffered
//  - h kept fp16 end-to-end: GEMM writes fp16, logits + aggregation read fp16
//  - aggregation gathers uint4 (8 halfs) per thread: half the L2 traffic
// ---------------------------------------------------------------------------

#define NN      30000
#define E_RAW   480000
#define E_TOT   (E_RAW + NN)
#define MAXF    512
#define NEG_SLOPE 0.2f

// ---- scratch (device globals) ---------------------------------------------
__device__ __half g_hA[NN * MAXF];              // fp16 activations (GEMM in)
__device__ __half g_hB[NN * MAXF];              // fp16 h (GEMM out)
__device__ __half g_wt[540672];                 // all transposed fp16 weights
__device__ float  g_as[NN * 4];
__device__ float  g_ad[NN * 4];
__device__ float  g_alpha[(size_t)E_TOT * 4];
__device__ int    g_deg[NN];
__device__ int    g_rowptr[NN + 1];
__device__ int    g_cursor[NN];
__device__ int    g_csrsrc[E_TOT];
__device__ int    g_is64;

// ---------------------------------------------------------------------------
// edge_index dtype detection (int32 vs int64)
// ---------------------------------------------------------------------------
__global__ void detect64_kernel(const int* __restrict__ words, int* flag) {
    if (threadIdx.x == 0 && blockIdx.x == 0) {
        int any = 0;
        #pragma unroll 4
        for (int i = 0; i < 256; i++) any |= words[2 * i + 1];
        *flag = (any == 0) ? 1 : 0;
    }
}

__device__ __forceinline__ void get_edge(const void* ei, int e, int is64,
                                         int& src, int& dst) {
    if (e >= E_RAW) { src = dst = e - E_RAW; return; }
    if (is64) {
        const long long* p = (const long long*)ei;
        src = (int)p[e];
        dst = (int)p[E_RAW + e];
    } else {
        const int* p = (const int*)ei;
        src = p[e];
        dst = p[E_RAW + e];
    }
}

// ---- CSR build ------------------------------------------------------------
__global__ void count_deg_kernel(const void* __restrict__ ei,
                                 const int* __restrict__ flag,
                                 int* __restrict__ deg) {
    int e = blockIdx.x * blockDim.x + threadIdx.x;
    if (e >= E_TOT) return;
    int src, dst;
    get_edge(ei, e, *flag, src, dst);
    atomicAdd(&deg[dst], 1);
}

__global__ void scan_kernel(const int* __restrict__ deg,
                            int* __restrict__ rowptr, int n) {
    __shared__ int sh[1024];
    __shared__ int carry_s;
    int t = threadIdx.x;
    if (t == 0) carry_s = 0;
    __syncthreads();
    for (int base = 0; base < n; base += 1024) {
        int i = base + t;
        int v = (i < n) ? deg[i] : 0;
        sh[t] = v;
        __syncthreads();
        for (int off = 1; off < 1024; off <<= 1) {
            int u = (t >= off) ? sh[t - off] : 0;
            __syncthreads();
            sh[t] += u;
            __syncthreads();
        }
        int carry = carry_s;
        if (i < n) rowptr[i] = carry + sh[t] - v;
        __syncthreads();
        if (t == 1023) carry_s = carry + sh[1023];
        __syncthreads();
    }
    if (t == 0) rowptr[n] = carry_s;
}

__global__ void fill_csr_kernel(const void* __restrict__ ei,
                                const int* __restrict__ flag,
                                int* __restrict__ cursor,
                                int* __restrict__ csrsrc) {
    int e = blockIdx.x * blockDim.x + threadIdx.x;
    if (e >= E_TOT) return;
    int src, dst;
    get_edge(ei, e, *flag, src, dst);
    int pos = atomicAdd(&cursor[dst], 1);
    csrsrc[pos] = src;
}

// ---- prep: fp32 -> fp16 convert, weight transpose -------------------------
__global__ void f2h_kernel(const float* __restrict__ in,
                           __half* __restrict__ out, int n) {
    int i = blockIdx.x * blockDim.x + threadIdx.x;
    int i4 = i * 4;
    if (i4 + 3 < n) {
        float4 v = *(const float4*)&in[i4];
        __half2 lo = __floats2half2_rn(v.x, v.y);
        __half2 hi = __floats2half2_rn(v.z, v.w);
        *(__half2*)&out[i4] = lo;
        *(__half2*)&out[i4 + 2] = hi;
    } else {
        for (int j = i4; j < n; j++) out[j] = __float2half_rn(in[j]);
    }
}

// W[K][N] fp32 -> Wt[N][K] fp16
__global__ void transpose_w_kernel(const float* __restrict__ W,
                                   __half* __restrict__ Wt, int K, int N) {
    __shared__ float tile[32][33];
    int k0 = blockIdx.y * 32, n0 = blockIdx.x * 32;
    int tx = threadIdx.x, ty = threadIdx.y;   // 32 x 8
    for (int i = ty; i < 32; i += 8) {
        int k = k0 + i, n = n0 + tx;
        tile[i][tx] = (k < K && n < N) ? W[(size_t)k * N + n] : 0.f;
    }
    __syncthreads();
    for (int i = ty; i < 32; i += 8) {
        int n = n0 + i, k = k0 + tx;
        if (n < N && k < K)
            Wt[(size_t)n * K + k] = __float2half_rn(tile[tx][i]);
    }
}

// ---------------------------------------------------------------------------
// fp16 tensor-core GEMM: C16[MxN] = round_f16(A16[MxK] * Wt16[NxK]^T)
// Block 128x128x32, 8 warps (2x4), warp tile 64x32, mma m16n8k16.
// ---------------------------------------------------------------------------
#define TBM 128
#define TBN 128
#define TBK 32
#define SAH 40

__device__ __forceinline__ void cp16(unsigned int smem, const void* gptr, int sz) {
    asm volatile("cp.async.cg.shared.global [%0], [%1], 16, %2;\n"
                 :: "r"(smem), "l"(gptr), "r"(sz));
}

__device__ __forceinline__ unsigned int smem_u32(const void* p) {
    return (unsigned int)__cvta_generic_to_shared(p);
}

__device__ __forceinline__ void mma_f16(float* d, const unsigned* a,
                                        const unsigned* b) {
    asm volatile(
        "mma.sync.aligned.m16n8k16.row.col.f32.f16.f16.f32 "
        "{%0,%1,%2,%3}, {%4,%5,%6,%7}, {%8,%9}, {%0,%1,%2,%3};\n"
        : "+f"(d[0]), "+f"(d[1]), "+f"(d[2]), "+f"(d[3])
        : "r"(a[0]), "r"(a[1]), "r"(a[2]), "r"(a[3]),
          "r"(b[0]), "r"(b[1]));
}

__global__ __launch_bounds__(256, 2)
void h16gemm_kernel(const __half* __restrict__ A, const __half* __restrict__ Bt,
                    __half* __restrict__ C, int M, int N, int K) {
    __shared__ __half As[2][TBM * SAH];
    __shared__ __half Bs[2][TBN * SAH];

    int tid  = threadIdx.x;
    int bm   = blockIdx.y * TBM;
    int bn   = blockIdx.x * TBN;
    int warp = tid >> 5;
    int lane = tid & 31;
    int wm   = (warp & 1) * 64;
    int wn   = (warp >> 1) * 32;
    int r    = lane >> 2;
    int c    = lane & 3;

    float acc[4][4][4];
    #pragma unroll
    for (int mi = 0; mi < 4; mi++)
        #pragma unroll
        for (int ni = 0; ni < 4; ni++)
            #pragma unroll
            for (int q = 0; q < 4; q++) acc[mi][ni][q] = 0.f;

    int row0 = tid >> 1;                  // 0..127
    int kc0  = (tid & 1) * 2;             // 0 or 2

    int niter = K / TBK;

    auto stage = [&](int buf, int k0) {
        #pragma unroll
        for (int j = 0; j < 2; j++) {
            int kc = kc0 + j;
            int smoff = (row0 * SAH + kc * 8) * 2;
            int ra = bm + row0;
            const __half* ga = A + (size_t)(ra < M ? ra : 0) * K + k0 + kc * 8;
            cp16(smem_u32(&As[buf][0]) + smoff, ga, ra < M ? 16 : 0);
            int rb = bn + row0;
            const __half* gb = Bt + (size_t)(rb < N ? rb : 0) * K + k0 + kc * 8;
            cp16(smem_u32(&Bs[buf][0]) + smoff, gb, rb < N ? 16 : 0);
        }
        asm volatile("cp.async.commit_group;\n");
    };

    stage(0, 0);

    for (int it = 0; it < niter; it++) {
        if (it + 1 < niter) {
            stage((it + 1) & 1, (it + 1) * TBK);
            asm volatile("cp.async.wait_group 1;\n");
        } else {
            asm volatile("cp.async.wait_group 0;\n");
        }
        __syncthreads();

        int buf = it & 1;
        #pragma unroll
        for (int kk = 0; kk < 2; kk++) {
            int kb = kk * 16;
            unsigned af[4][4];
            #pragma unroll
            for (int mi = 0; mi < 4; mi++) {
                const __half* ap = &As[buf][(wm + mi * 16 + r) * SAH + kb + 2 * c];
                af[mi][0] = *(const unsigned*)(ap);
                af[mi][1] = *(const unsigned*)(ap + 8 * SAH);
                af[mi][2] = *(const unsigned*)(ap + 8);
                af[mi][3] = *(const unsigned*)(ap + 8 * SAH + 8);
            }
            unsigned bf[4][2];
            #pragma unroll
            for (int ni = 0; ni < 4; ni++) {
                const __half* bp = &Bs[buf][(wn + ni * 8 + r) * SAH + kb + 2 * c];
                bf[ni][0] = *(const unsigned*)(bp);
                bf[ni][1] = *(const unsigned*)(bp + 8);
            }
            #pragma unroll
            for (int mi = 0; mi < 4; mi++)
                #pragma unroll
                for (int ni = 0; ni < 4; ni++)
                    mma_f16(acc[mi][ni], af[mi], bf[ni]);
        }
        __syncthreads();
    }

    // epilogue: fp16 stores (half2 per row pair of cols)
    #pragma unroll
    for (int mi = 0; mi < 4; mi++) {
        int m0 = bm + wm + mi * 16 + r;
        #pragma unroll
        for (int ni = 0; ni < 4; ni++) {
            int n0 = bn + wn + ni * 8 + 2 * c;
            if (n0 < N) {
                if (m0 < M) {
                    __half2 v = __floats2half2_rn(acc[mi][ni][0], acc[mi][ni][1]);
                    *(__half2*)&C[(size_t)m0 * N + n0] = v;
                }
                if (m0 + 8 < M) {
                    __half2 v = __floats2half2_rn(acc[mi][ni][2], acc[mi][ni][3]);
                    *(__half2*)&C[(size_t)(m0 + 8) * N + n0] = v;
                }
            }
        }
    }
}

// ---- per-node attention logits (fp16 h, fp32 accum) -----------------------
__global__ void node_alpha_kernel(const __half* __restrict__ h,
                                  const float* __restrict__ a_s,
                                  const float* __restrict__ a_d,
                                  float* __restrict__ out_s,
                                  float* __restrict__ out_d,
                                  int H, int C) {
    int warp = (blockIdx.x * blockDim.x + threadIdx.x) >> 5;
    int lane = threadIdx.x & 31;
    if (warp >= NN * H) return;
    int n = warp / H;
    int hd = warp - n * H;
    const __half* hp = h + (size_t)n * H * C + (size_t)hd * C;
    const float* asv = a_s + (size_t)hd * C;
    const float* adv = a_d + (size_t)hd * C;
    float s = 0.f, d = 0.f;
    for (int cc = lane * 2; cc < C; cc += 64) {
        float2 v = __half22float2(*(const __half2*)&hp[cc]);
        s = fmaf(v.x, asv[cc], s);
        s = fmaf(v.y, asv[cc + 1], s);
        d = fmaf(v.x, adv[cc], d);
        d = fmaf(v.y, adv[cc + 1], d);
    }
    #pragma unroll
    for (int o = 16; o > 0; o >>= 1) {
        s += __shfl_xor_sync(0xffffffffu, s, o);
        d += __shfl_xor_sync(0xffffffffu, d, o);
    }
    if (lane == 0) {
        out_s[n * H + hd] = s;
        out_d[n * H + hd] = d;
    }
}

// ---- edge softmax ---------------------------------------------------------
__device__ __forceinline__ float leaky(float x) {
    return x > 0.f ? x : NEG_SLOPE * x;
}

__global__ void edge_softmax_kernel(const int* __restrict__ rowptr,
                                    const int* __restrict__ csrsrc,
                                    const float* __restrict__ as_,
                                    const float* __restrict__ ad_,
                                    float* __restrict__ alpha, int H) {
    int warp = (blockIdx.x * blockDim.x + threadIdx.x) >> 5;
    int lane = threadIdx.x & 31;
    if (warp >= NN * H) return;
    int d = warp / H;
    int hd = warp - d * H;
    int s0 = rowptr[d], s1 = rowptr[d + 1];
    float adv = ad_[d * H + hd];

    float mx = -3.0e38f;
    for (int p = s0 + lane; p < s1; p += 32) {
        float e = leaky(as_[csrsrc[p] * H + hd] + adv);
        mx = fmaxf(mx, e);
    }
    #pragma unroll
    for (int o = 16; o > 0; o >>= 1)
        mx = fmaxf(mx, __shfl_xor_sync(0xffffffffu, mx, o));

    float sum = 0.f;
    for (int p = s0 + lane; p < s1; p += 32) {
        float e = leaky(as_[csrsrc[p] * H + hd] + adv);
        float ex = expf(e - mx);
        alpha[(size_t)p * H + hd] = ex;
        sum += ex;
    }
    #pragma unroll
    for (int o = 16; o > 0; o >>= 1)
        sum += __shfl_xor_sync(0xffffffffu, sum, o);
    float inv = 1.f / sum;

    for (int p = s0 + lane; p < s1; p += 32)
        alpha[(size_t)p * H + hd] *= inv;
}

// ---- aggregation: out = relu(sum alpha*h16 + b), fp16 or fp32 output ------
// thread handles 8 features (uint4 = 8 halfs); blockDim.y dsts per block.
template <bool F16OUT>
__global__ __launch_bounds__(256)
void aggregate_kernel(const __half* __restrict__ h,
                      const float* __restrict__ alpha,
                      const int* __restrict__ rowptr,
                      const int* __restrict__ csrsrc,
                      const float* __restrict__ bias,
                      float* __restrict__ out32,
                      __half* __restrict__ out16,
                      int H, int HC, int logC) {
    int d = blockIdx.x * blockDim.y + threadIdx.y;
    if (d >= NN) return;
    int f = threadIdx.x * 8;
    int head = f >> logC;

    float acc[8];
    #pragma unroll
    for (int q = 0; q < 8; q++) acc[q] = 0.f;

    int s0 = rowptr[d], s1 = rowptr[d + 1];
    for (int p = s0; p < s1; p++) {
        int src = csrsrc[p];
        float a = alpha[(size_t)p * H + head];
        uint4 raw = *(const uint4*)&h[(size_t)src * HC + f];
        float2 v0 = __half22float2(*(__half2*)&raw.x);
        float2 v1 = __half22float2(*(__half2*)&raw.y);
        float2 v2 = __half22float2(*(__half2*)&raw.z);
        float2 v3 = __half22float2(*(__half2*)&raw.w);
        acc[0] = fmaf(v0.x, a, acc[0]);
        acc[1] = fmaf(v0.y, a, acc[1]);
        acc[2] = fmaf(v1.x, a, acc[2]);
        acc[3] = fmaf(v1.y, a, acc[3]);
        acc[4] = fmaf(v2.x, a, acc[4]);
        acc[5] = fmaf(v2.y, a, acc[5]);
        acc[6] = fmaf(v3.x, a, acc[6]);
        acc[7] = fmaf(v3.y, a, acc[7]);
    }
    float4 b0 = *(const float4*)&bias[f];
    float4 b1 = *(const float4*)&bias[f + 4];
    float o[8];
    o[0] = fmaxf(acc[0] + b0.x, 0.f);
    o[1] = fmaxf(acc[1] + b0.y, 0.f);
    o[2] = fmaxf(acc[2] + b0.z, 0.f);
    o[3] = fmaxf(acc[3] + b0.w, 0.f);
    o[4] = fmaxf(acc[4] + b1.x, 0.f);
    o[5] = fmaxf(acc[5] + b1.y, 0.f);
    o[6] = fmaxf(acc[6] + b1.z, 0.f);
    o[7] = fmaxf(acc[7] + b1.w, 0.f);
    if (F16OUT) {
        uint4 packed;
        *(__half2*)&packed.x = __floats2half2_rn(o[0], o[1]);
        *(__half2*)&packed.y = __floats2half2_rn(o[2], o[3]);
        *(__half2*)&packed.z = __floats2half2_rn(o[4], o[5]);
        *(__half2*)&packed.w = __floats2half2_rn(o[6], o[7]);
        *(uint4*)&out16[(size_t)d * HC + f] = packed;
    } else {
        float4 lo = make_float4(o[0], o[1], o[2], o[3]);
        float4 hi = make_float4(o[4], o[5], o[6], o[7]);
        *(float4*)&out32[(size_t)d * HC + f] = lo;
        *(float4*)&out32[(size_t)d * HC + f + 4] = hi;
    }
}

// ---------------------------------------------------------------------------
// host side
// ---------------------------------------------------------------------------
static inline void run_gemm(const __half* A, const __half* Bt, __half* C,
                            int M, int N, int K) {
    dim3 grid((N + TBN - 1) / TBN, (M + TBM - 1) / TBM);
    h16gemm_kernel<<<grid, 256>>>(A, Bt, C, M, N, K);
}

static inline void run_aggregate(const __half* h, const float* alpha,
                                 const int* rowptr, const int* csrsrc,
                                 const float* bias, float* out32,
                                 __half* out16, int H, int HC, int logC) {
    int tx = HC / 8;
    int ty = 256 / tx;
    dim3 block(tx, ty);
    dim3 grid((NN + ty - 1) / ty);
    if (out16)
        aggregate_kernel<true><<<grid, block>>>(h, alpha, rowptr, csrsrc,
                                                bias, nullptr, out16, H, HC, logC);
    else
        aggregate_kernel<false><<<grid, block>>>(h, alpha, rowptr, csrsrc,
                                                 bias, out32, nullptr, H, HC, logC);
}

static inline void run_transpose(const float* W, __half* Wt, int K, int N) {
    dim3 grid((N + 31) / 32, (K + 31) / 32);
    transpose_w_kernel<<<grid, dim3(32, 8)>>>(W, Wt, K, N);
}

extern "C" void kernel_launch(void* const* d_in, const int* in_sizes, int n_in,
                              void* d_out, int out_size) {
    const float* x   = (const float*)d_in[0];
    const void*  ei  = d_in[1];
    const float* W1  = (const float*)d_in[2];
    const float* a1s = (const float*)d_in[3];
    const float* a1d = (const float*)d_in[4];
    const float* b1  = (const float*)d_in[5];
    const float* W2  = (const float*)d_in[6];
    const float* a2s = (const float*)d_in[7];
    const float* a2d = (const float*)d_in[8];
    const float* b2  = (const float*)d_in[9];
    const float* W3  = (const float*)d_in[10];
    const float* a3s = (const float*)d_in[11];
    const float* a3d = (const float*)d_in[12];
    const float* b3  = (const float*)d_in[13];
    const float* W4  = (const float*)d_in[14];
    const float* a4s = (const float*)d_in[15];
    const float* a4d = (const float*)d_in[16];
    const float* b4  = (const float*)d_in[17];
    float* out = (float*)d_out;

    float *asb, *adb, *alpha;
    __half *hA, *hB, *wt;
    int *deg, *rowptr, *cursor, *csrsrc, *is64;
    cudaGetSymbolAddress((void**)&hA, g_hA);
    cudaGetSymbolAddress((void**)&hB, g_hB);
    cudaGetSymbolAddress((void**)&wt, g_wt);
    cudaGetSymbolAddress((void**)&asb, g_as);
    cudaGetSymbolAddress((void**)&adb, g_ad);
    cudaGetSymbolAddress((void**)&alpha, g_alpha);
    cudaGetSymbolAddress((void**)&deg, g_deg);
    cudaGetSymbolAddress((void**)&rowptr, g_rowptr);
    cudaGetSymbolAddress((void**)&cursor, g_cursor);
    cudaGetSymbolAddress((void**)&csrsrc, g_csrsrc);
    cudaGetSymbolAddress((void**)&is64, g_is64);

    __half* wt1 = wt;                     // [512][256]
    __half* wt2 = wt + 131072;            // [512][512]
    __half* wt3 = wt + 131072 + 262144;   // [256][512]
    __half* wt4 = wt + 131072 + 262144 + 131072;  // [64][256]

    // ---- prep: CSR + dtype conversions (graph identical across layers) ----
    cudaMemsetAsync(deg, 0, NN * sizeof(int));
    detect64_kernel<<<1, 32>>>((const int*)ei, is64);
    count_deg_kernel<<<(E_TOT + 255) / 256, 256>>>(ei, is64, deg);
    scan_kernel<<<1, 1024>>>(deg, rowptr, NN);
    cudaMemcpyAsync(cursor, rowptr, NN * sizeof(int), cudaMemcpyDeviceToDevice);
    fill_csr_kernel<<<(E_TOT + 255) / 256, 256>>>(ei, is64, cursor, csrsrc);

    f2h_kernel<<<(NN * 256 / 4 + 255) / 256, 256>>>(x, hA, NN * 256);
    run_transpose(W1, wt1, 256, 512);
    run_transpose(W2, wt2, 512, 512);
    run_transpose(W3, wt3, 512, 256);
    run_transpose(W4, wt4, 256, 64);

    auto nblocks_warps = [](int warps) { return (warps + 7) / 8; };

    // ---- layer 1: 256 -> 4x128 ----
    run_gemm(hA, wt1, hB, NN, 512, 256);
    node_alpha_kernel<<<nblocks_warps(NN * 4), 256>>>(hB, a1s, a1d, asb, adb, 4, 128);
    edge_softmax_kernel<<<nblocks_warps(NN * 4), 256>>>(rowptr, csrsrc, asb, adb, alpha, 4);
    run_aggregate(hB, alpha, rowptr, csrsrc, b1, nullptr, hA, 4, 512, 7);

    // ---- layer 2: 512 -> 4x128 ----
    run_gemm(hA, wt2, hB, NN, 512, 512);
    node_alpha_kernel<<<nblocks_warps(NN * 4), 256>>>(hB, a2s, a2d, asb, adb, 4, 128);
    edge_softmax_kernel<<<nblocks_warps(NN * 4), 256>>>(rowptr, csrsrc, asb, adb, alpha, 4);
    run_aggregate(hB, alpha, rowptr, csrsrc, b2, nullptr, hA, 4, 512, 7);

    // ---- layer 3: 512 -> 4x64 ----
    run_gemm(hA, wt3, hB, NN, 256, 512);
    node_alpha_kernel<<<nblocks_warps(NN * 4), 256>>>(hB, a3s, a3d, asb, adb, 4, 64);
    edge_softmax_kernel<<<nblocks_warps(NN * 4), 256>>>(rowptr, csrsrc, asb, adb, alpha, 4);
    run_aggregate(hB, alpha, rowptr, csrsrc, b3, nullptr, hA, 4, 256, 6);

    // ---- layer 4: 256 -> 1x64, concat=False ----
    run_gemm(hA, wt4, hB, NN, 64, 256);
    node_alpha_kernel<<<nblocks_warps(NN * 1), 256>>>(hB, a4s, a4d, asb, adb, 1, 64);
    edge_softmax_kernel<<<nblocks_warps(NN * 1), 256>>>(rowptr, csrsrc, asb, adb, alpha, 1);
    run_aggregate(hB, alpha, rowptr, csrsrc, b4, out, nullptr, 1, 64, 6);

    (void)in_sizes; (void)n_in; (void)out_size;
}

// round 6
// speedup vs baseline: 1.3910x; 1.3910x over previous
#include <cuda_runtime.h>
#include <cuda_fp16.h>
#include <cstdint>
#include <math.h>

// ---------------------------------------------------------------------------
// GAT 4-layer stack on GB300, round 6:
//  - fp16 mma.sync m16n8k16 GEMM, fp32 accum, cp.async double-buffered
//  - h fp16 end-to-end
//  - aggregation: uint2 (4 halfs)/thread -> full thread parallelism restored,
//    2-edge manual unroll for MLP. (round 5's 8-halfs/thread halved the
//    thread count and made the latency-bound gather 2x slower)
// ---------------------------------------------------------------------------

#define NN      30000
#define E_RAW   480000
#define E_TOT   (E_RAW + NN)
#define MAXF    512
#define NEG_SLOPE 0.2f

// ---- scratch (device globals) ---------------------------------------------
__device__ __half g_hA[NN * MAXF];              // fp16 activations (GEMM in)
__device__ __half g_hB[NN * MAXF];              // fp16 h (GEMM out)
__device__ __half g_wt[540672];                 // all transposed fp16 weights
__device__ float  g_as[NN * 4];
__device__ float  g_ad[NN * 4];
__device__ float  g_alpha[(size_t)E_TOT * 4];
__device__ int    g_deg[NN];
__device__ int    g_rowptr[NN + 1];
__device__ int    g_cursor[NN];
__device__ int    g_csrsrc[E_TOT];
__device__ int    g_is64;

// ---------------------------------------------------------------------------
// edge_index dtype detection (int32 vs int64)
// ---------------------------------------------------------------------------
__global__ void detect64_kernel(const int* __restrict__ words, int* flag) {
    if (threadIdx.x == 0 && blockIdx.x == 0) {
        int any = 0;
        #pragma unroll 4
        for (int i = 0; i < 256; i++) any |= words[2 * i + 1];
        *flag = (any == 0) ? 1 : 0;
    }
}

__device__ __forceinline__ void get_edge(const void* ei, int e, int is64,
                                         int& src, int& dst) {
    if (e >= E_RAW) { src = dst = e - E_RAW; return; }
    if (is64) {
        const long long* p = (const long long*)ei;
        src = (int)p[e];
        dst = (int)p[E_RAW + e];
    } else {
        const int* p = (const int*)ei;
        src = p[e];
        dst = p[E_RAW + e];
    }
}

// ---- CSR build ------------------------------------------------------------
__global__ void count_deg_kernel(const void* __restrict__ ei,
                                 const int* __restrict__ flag,
                                 int* __restrict__ deg) {
    int e = blockIdx.x * blockDim.x + threadIdx.x;
    if (e >= E_TOT) return;
    int src, dst;
    get_edge(ei, e, *flag, src, dst);
    atomicAdd(&deg[dst], 1);
}

__global__ void scan_kernel(const int* __restrict__ deg,
                            int* __restrict__ rowptr, int n) {
    __shared__ int sh[1024];
    __shared__ int carry_s;
    int t = threadIdx.x;
    if (t == 0) carry_s = 0;
    __syncthreads();
    for (int base = 0; base < n; base += 1024) {
        int i = base + t;
        int v = (i < n) ? deg[i] : 0;
        sh[t] = v;
        __syncthreads();
        for (int off = 1; off < 1024; off <<= 1) {
            int u = (t >= off) ? sh[t - off] : 0;
            __syncthreads();
            sh[t] += u;
            __syncthreads();
        }
        int carry = carry_s;
        if (i < n) rowptr[i] = carry + sh[t] - v;
        __syncthreads();
        if (t == 1023) carry_s = carry + sh[1023];
        __syncthreads();
    }
    if (t == 0) rowptr[n] = carry_s;
}

__global__ void fill_csr_kernel(const void* __restrict__ ei,
                                const int* __restrict__ flag,
                                int* __restrict__ cursor,
                                int* __restrict__ csrsrc) {
    int e = blockIdx.x * blockDim.x + threadIdx.x;
    if (e >= E_TOT) return;
    int src, dst;
    get_edge(ei, e, *flag, src, dst);
    int pos = atomicAdd(&cursor[dst], 1);
    csrsrc[pos] = src;
}

// ---- prep: fp32 -> fp16 convert, weight transpose -------------------------
__global__ void f2h_kernel(const float* __restrict__ in,
                           __half* __restrict__ out, int n) {
    int i = blockIdx.x * blockDim.x + threadIdx.x;
    int i4 = i * 4;
    if (i4 + 3 < n) {
        float4 v = *(const float4*)&in[i4];
        __half2 lo = __floats2half2_rn(v.x, v.y);
        __half2 hi = __floats2half2_rn(v.z, v.w);
        *(__half2*)&out[i4] = lo;
        *(__half2*)&out[i4 + 2] = hi;
    } else {
        for (int j = i4; j < n; j++) out[j] = __float2half_rn(in[j]);
    }
}

// W[K][N] fp32 -> Wt[N][K] fp16
__global__ void transpose_w_kernel(const float* __restrict__ W,
                                   __half* __restrict__ Wt, int K, int N) {
    __shared__ float tile[32][33];
    int k0 = blockIdx.y * 32, n0 = blockIdx.x * 32;
    int tx = threadIdx.x, ty = threadIdx.y;   // 32 x 8
    for (int i = ty; i < 32; i += 8) {
        int k = k0 + i, n = n0 + tx;
        tile[i][tx] = (k < K && n < N) ? W[(size_t)k * N + n] : 0.f;
    }
    __syncthreads();
    for (int i = ty; i < 32; i += 8) {
        int n = n0 + i, k = k0 + tx;
        if (n < N && k < K)
            Wt[(size_t)n * K + k] = __float2half_rn(tile[tx][i]);
    }
}

// ---------------------------------------------------------------------------
// fp16 tensor-core GEMM: C16[MxN] = round_f16(A16[MxK] * Wt16[NxK]^T)
// Block 128x128x32, 8 warps (2x4), warp tile 64x32, mma m16n8k16.
// ---------------------------------------------------------------------------
#define TBM 128
#define TBN 128
#define TBK 32
#define SAH 40

__device__ __forceinline__ void cp16(unsigned int smem, const void* gptr, int sz) {
    asm volatile("cp.async.cg.shared.global [%0], [%1], 16, %2;\n"
                 :: "r"(smem), "l"(gptr), "r"(sz));
}

__device__ __forceinline__ unsigned int smem_u32(const void* p) {
    return (unsigned int)__cvta_generic_to_shared(p);
}

__device__ __forceinline__ void mma_f16(float* d, const unsigned* a,
                                        const unsigned* b) {
    asm volatile(
        "mma.sync.aligned.m16n8k16.row.col.f32.f16.f16.f32 "
        "{%0,%1,%2,%3}, {%4,%5,%6,%7}, {%8,%9}, {%0,%1,%2,%3};\n"
        : "+f"(d[0]), "+f"(d[1]), "+f"(d[2]), "+f"(d[3])
        : "r"(a[0]), "r"(a[1]), "r"(a[2]), "r"(a[3]),
          "r"(b[0]), "r"(b[1]));
}

__global__ __launch_bounds__(256, 2)
void h16gemm_kernel(const __half* __restrict__ A, const __half* __restrict__ Bt,
                    __half* __restrict__ C, int M, int N, int K) {
    __shared__ __half As[2][TBM * SAH];
    __shared__ __half Bs[2][TBN * SAH];

    int tid  = threadIdx.x;
    int bm   = blockIdx.y * TBM;
    int bn   = blockIdx.x * TBN;
    int warp = tid >> 5;
    int lane = tid & 31;
    int wm   = (warp & 1) * 64;
    int wn   = (warp >> 1) * 32;
    int r    = lane >> 2;
    int c    = lane & 3;

    float acc[4][4][4];
    #pragma unroll
    for (int mi = 0; mi < 4; mi++)
        #pragma unroll
        for (int ni = 0; ni < 4; ni++)
            #pragma unroll
            for (int q = 0; q < 4; q++) acc[mi][ni][q] = 0.f;

    int row0 = tid >> 1;                  // 0..127
    int kc0  = (tid & 1) * 2;             // 0 or 2

    int niter = K / TBK;

    auto stage = [&](int buf, int k0) {
        #pragma unroll
        for (int j = 0; j < 2; j++) {
            int kc = kc0 + j;
            int smoff = (row0 * SAH + kc * 8) * 2;
            int ra = bm + row0;
            const __half* ga = A + (size_t)(ra < M ? ra : 0) * K + k0 + kc * 8;
            cp16(smem_u32(&As[buf][0]) + smoff, ga, ra < M ? 16 : 0);
            int rb = bn + row0;
            const __half* gb = Bt + (size_t)(rb < N ? rb : 0) * K + k0 + kc * 8;
            cp16(smem_u32(&Bs[buf][0]) + smoff, gb, rb < N ? 16 : 0);
        }
        asm volatile("cp.async.commit_group;\n");
    };

    stage(0, 0);

    for (int it = 0; it < niter; it++) {
        if (it + 1 < niter) {
            stage((it + 1) & 1, (it + 1) * TBK);
            asm volatile("cp.async.wait_group 1;\n");
        } else {
            asm volatile("cp.async.wait_group 0;\n");
        }
        __syncthreads();

        int buf = it & 1;
        #pragma unroll
        for (int kk = 0; kk < 2; kk++) {
            int kb = kk * 16;
            unsigned af[4][4];
            #pragma unroll
            for (int mi = 0; mi < 4; mi++) {
                const __half* ap = &As[buf][(wm + mi * 16 + r) * SAH + kb + 2 * c];
                af[mi][0] = *(const unsigned*)(ap);
                af[mi][1] = *(const unsigned*)(ap + 8 * SAH);
                af[mi][2] = *(const unsigned*)(ap + 8);
                af[mi][3] = *(const unsigned*)(ap + 8 * SAH + 8);
            }
            unsigned bf[4][2];
            #pragma unroll
            for (int ni = 0; ni < 4; ni++) {
                const __half* bp = &Bs[buf][(wn + ni * 8 + r) * SAH + kb + 2 * c];
                bf[ni][0] = *(const unsigned*)(bp);
                bf[ni][1] = *(const unsigned*)(bp + 8);
            }
            #pragma unroll
            for (int mi = 0; mi < 4; mi++)
                #pragma unroll
                for (int ni = 0; ni < 4; ni++)
                    mma_f16(acc[mi][ni], af[mi], bf[ni]);
        }
        __syncthreads();
    }

    // epilogue: fp16 stores
    #pragma unroll
    for (int mi = 0; mi < 4; mi++) {
        int m0 = bm + wm + mi * 16 + r;
        #pragma unroll
        for (int ni = 0; ni < 4; ni++) {
            int n0 = bn + wn + ni * 8 + 2 * c;
            if (n0 < N) {
                if (m0 < M) {
                    __half2 v = __floats2half2_rn(acc[mi][ni][0], acc[mi][ni][1]);
                    *(__half2*)&C[(size_t)m0 * N + n0] = v;
                }
                if (m0 + 8 < M) {
                    __half2 v = __floats2half2_rn(acc[mi][ni][2], acc[mi][ni][3]);
                    *(__half2*)&C[(size_t)(m0 + 8) * N + n0] = v;
                }
            }
        }
    }
}

// ---- per-node attention logits (fp16 h, fp32 accum) -----------------------
__global__ void node_alpha_kernel(const __half* __restrict__ h,
                                  const float* __restrict__ a_s,
                                  const float* __restrict__ a_d,
                                  float* __restrict__ out_s,
                                  float* __restrict__ out_d,
                                  int H, int C) {
    int warp = (blockIdx.x * blockDim.x + threadIdx.x) >> 5;
    int lane = threadIdx.x & 31;
    if (warp >= NN * H) return;
    int n = warp / H;
    int hd = warp - n * H;
    const __half* hp = h + (size_t)n * H * C + (size_t)hd * C;
    const float* asv = a_s + (size_t)hd * C;
    const float* adv = a_d + (size_t)hd * C;
    float s = 0.f, d = 0.f;
    for (int cc = lane * 2; cc < C; cc += 64) {
        float2 v = __half22float2(*(const __half2*)&hp[cc]);
        s = fmaf(v.x, asv[cc], s);
        s = fmaf(v.y, asv[cc + 1], s);
        d = fmaf(v.x, adv[cc], d);
        d = fmaf(v.y, adv[cc + 1], d);
    }
    #pragma unroll
    for (int o = 16; o > 0; o >>= 1) {
        s += __shfl_xor_sync(0xffffffffu, s, o);
        d += __shfl_xor_sync(0xffffffffu, d, o);
    }
    if (lane == 0) {
        out_s[n * H + hd] = s;
        out_d[n * H + hd] = d;
    }
}

// ---- edge softmax ---------------------------------------------------------
__device__ __forceinline__ float leaky(float x) {
    return x > 0.f ? x : NEG_SLOPE * x;
}

__global__ void edge_softmax_kernel(const int* __restrict__ rowptr,
                                    const int* __restrict__ csrsrc,
                                    const float* __restrict__ as_,
                                    const float* __restrict__ ad_,
                                    float* __restrict__ alpha, int H) {
    int warp = (blockIdx.x * blockDim.x + threadIdx.x) >> 5;
    int lane = threadIdx.x & 31;
    if (warp >= NN * H) return;
    int d = warp / H;
    int hd = warp - d * H;
    int s0 = rowptr[d], s1 = rowptr[d + 1];
    float adv = ad_[d * H + hd];

    float mx = -3.0e38f;
    for (int p = s0 + lane; p < s1; p += 32) {
        float e = leaky(as_[csrsrc[p] * H + hd] + adv);
        mx = fmaxf(mx, e);
    }
    #pragma unroll
    for (int o = 16; o > 0; o >>= 1)
        mx = fmaxf(mx, __shfl_xor_sync(0xffffffffu, mx, o));

    float sum = 0.f;
    for (int p = s0 + lane; p < s1; p += 32) {
        float e = leaky(as_[csrsrc[p] * H + hd] + adv);
        float ex = expf(e - mx);
        alpha[(size_t)p * H + hd] = ex;
        sum += ex;
    }
    #pragma unroll
    for (int o = 16; o > 0; o >>= 1)
        sum += __shfl_xor_sync(0xffffffffu, sum, o);
    float inv = 1.f / sum;

    for (int p = s0 + lane; p < s1; p += 32)
        alpha[(size_t)p * H + hd] *= inv;
}

// ---- aggregation: out = relu(sum alpha*h16 + b) ---------------------------
// 4 halfs (uint2) per thread, 2-edge unroll for MLP; tx = HC/4 threads/dst.
template <bool F16OUT>
__global__ __launch_bounds__(256)
void aggregate_kernel(const __half* __restrict__ h,
                      const float* __restrict__ alpha,
                      const int* __restrict__ rowptr,
                      const int* __restrict__ csrsrc,
                      const float* __restrict__ bias,
                      float* __restrict__ out32,
                      __half* __restrict__ out16,
                      int H, int HC, int logC) {
    int d = blockIdx.x * blockDim.y + threadIdx.y;
    if (d >= NN) return;
    int f = threadIdx.x * 4;
    int head = f >> logC;

    float acc0 = 0.f, acc1 = 0.f, acc2 = 0.f, acc3 = 0.f;
    int s0 = rowptr[d], s1 = rowptr[d + 1];
    int p = s0;
    for (; p + 1 < s1; p += 2) {
        int srcA = csrsrc[p];
        int srcB = csrsrc[p + 1];
        float aA = alpha[(size_t)p * H + head];
        float aB = alpha[(size_t)(p + 1) * H + head];
        uint2 rA = *(const uint2*)&h[(size_t)srcA * HC + f];
        uint2 rB = *(const uint2*)&h[(size_t)srcB * HC + f];
        float2 vA0 = __half22float2(*(__half2*)&rA.x);
        float2 vA1 = __half22float2(*(__half2*)&rA.y);
        float2 vB0 = __half22float2(*(__half2*)&rB.x);
        float2 vB1 = __half22float2(*(__half2*)&rB.y);
        acc0 = fmaf(vA0.x, aA, fmaf(vB0.x, aB, acc0));
        acc1 = fmaf(vA0.y, aA, fmaf(vB0.y, aB, acc1));
        acc2 = fmaf(vA1.x, aA, fmaf(vB1.x, aB, acc2));
        acc3 = fmaf(vA1.y, aA, fmaf(vB1.y, aB, acc3));
    }
    if (p < s1) {
        int src = csrsrc[p];
        float a = alpha[(size_t)p * H + head];
        uint2 raw = *(const uint2*)&h[(size_t)src * HC + f];
        float2 v0 = __half22float2(*(__half2*)&raw.x);
        float2 v1 = __half22float2(*(__half2*)&raw.y);
        acc0 = fmaf(v0.x, a, acc0);
        acc1 = fmaf(v0.y, a, acc1);
        acc2 = fmaf(v1.x, a, acc2);
        acc3 = fmaf(v1.y, a, acc3);
    }

    float4 b = *(const float4*)&bias[f];
    float o0 = fmaxf(acc0 + b.x, 0.f);
    float o1 = fmaxf(acc1 + b.y, 0.f);
    float o2 = fmaxf(acc2 + b.z, 0.f);
    float o3 = fmaxf(acc3 + b.w, 0.f);
    if (F16OUT) {
        uint2 packed;
        *(__half2*)&packed.x = __floats2half2_rn(o0, o1);
        *(__half2*)&packed.y = __floats2half2_rn(o2, o3);
        *(uint2*)&out16[(size_t)d * HC + f] = packed;
    } else {
        float4 o = make_float4(o0, o1, o2, o3);
        *(float4*)&out32[(size_t)d * HC + f] = o;
    }
}

// ---------------------------------------------------------------------------
// host side
// ---------------------------------------------------------------------------
static inline void run_gemm(const __half* A, const __half* Bt, __half* C,
                            int M, int N, int K) {
    dim3 grid((N + TBN - 1) / TBN, (M + TBM - 1) / TBM);
    h16gemm_kernel<<<grid, 256>>>(A, Bt, C, M, N, K);
}

static inline void run_aggregate(const __half* h, const float* alpha,
                                 const int* rowptr, const int* csrsrc,
                                 const float* bias, float* out32,
                                 __half* out16, int H, int HC, int logC) {
    int tx = HC / 4;
    int ty = 256 / tx;
    dim3 block(tx, ty);
    dim3 grid((NN + ty - 1) / ty);
    if (out16)
        aggregate_kernel<true><<<grid, block>>>(h, alpha, rowptr, csrsrc,
                                                bias, nullptr, out16, H, HC, logC);
    else
        aggregate_kernel<false><<<grid, block>>>(h, alpha, rowptr, csrsrc,
                                                 bias, out32, nullptr, H, HC, logC);
}

static inline void run_transpose(const float* W, __half* Wt, int K, int N) {
    dim3 grid((N + 31) / 32, (K + 31) / 32);
    transpose_w_kernel<<<grid, dim3(32, 8)>>>(W, Wt, K, N);
}

extern "C" void kernel_launch(void* const* d_in, const int* in_sizes, int n_in,
                              void* d_out, int out_size) {
    const float* x   = (const float*)d_in[0];
    const void*  ei  = d_in[1];
    const float* W1  = (const float*)d_in[2];
    const float* a1s = (const float*)d_in[3];
    const float* a1d = (const float*)d_in[4];
    const float* b1  = (const float*)d_in[5];
    const float* W2  = (const float*)d_in[6];
    const float* a2s = (const float*)d_in[7];
    const float* a2d = (const float*)d_in[8];
    const float* b2  = (const float*)d_in[9];
    const float* W3  = (const float*)d_in[10];
    const float* a3s = (const float*)d_in[11];
    const float* a3d = (const float*)d_in[12];
    const float* b3  = (const float*)d_in[13];
    const float* W4  = (const float*)d_in[14];
    const float* a4s = (const float*)d_in[15];
    const float* a4d = (const float*)d_in[16];
    const float* b4  = (const float*)d_in[17];
    float* out = (float*)d_out;

    float *asb, *adb, *alpha;
    __half *hA, *hB, *wt;
    int *deg, *rowptr, *cursor, *csrsrc, *is64;
    cudaGetSymbolAddress((void**)&hA, g_hA);
    cudaGetSymbolAddress((void**)&hB, g_hB);
    cudaGetSymbolAddress((void**)&wt, g_wt);
    cudaGetSymbolAddress((void**)&asb, g_as);
    cudaGetSymbolAddress((void**)&adb, g_ad);
    cudaGetSymbolAddress((void**)&alpha, g_alpha);
    cudaGetSymbolAddress((void**)&deg, g_deg);
    cudaGetSymbolAddress((void**)&rowptr, g_rowptr);
    cudaGetSymbolAddress((void**)&cursor, g_cursor);
    cudaGetSymbolAddress((void**)&csrsrc, g_csrsrc);
    cudaGetSymbolAddress((void**)&is64, g_is64);

    __half* wt1 = wt;                     // [512][256]
    __half* wt2 = wt + 131072;            // [512][512]
    __half* wt3 = wt + 131072 + 262144;   // [256][512]
    __half* wt4 = wt + 131072 + 262144 + 131072;  // [64][256]

    // ---- prep: CSR + dtype conversions ----
    cudaMemsetAsync(deg, 0, NN * sizeof(int));
    detect64_kernel<<<1, 32>>>((const int*)ei, is64);
    count_deg_kernel<<<(E_TOT + 255) / 256, 256>>>(ei, is64, deg);
    scan_kernel<<<1, 1024>>>(deg, rowptr, NN);
    cudaMemcpyAsync(cursor, rowptr, NN * sizeof(int), cudaMemcpyDeviceToDevice);
    fill_csr_kernel<<<(E_TOT + 255) / 256, 256>>>(ei, is64, cursor, csrsrc);

    f2h_kernel<<<(NN * 256 / 4 + 255) / 256, 256>>>(x, hA, NN * 256);
    run_transpose(W1, wt1, 256, 512);
    run_transpose(W2, wt2, 512, 512);
    run_transpose(W3, wt3, 512, 256);
    run_transpose(W4, wt4, 256, 64);

    auto nblocks_warps = [](int warps) { return (warps + 7) / 8; };

    // ---- layer 1: 256 -> 4x128 ----
    run_gemm(hA, wt1, hB, NN, 512, 256);
    node_alpha_kernel<<<nblocks_warps(NN * 4), 256>>>(hB, a1s, a1d, asb, adb, 4, 128);
    edge_softmax_kernel<<<nblocks_warps(NN * 4), 256>>>(rowptr, csrsrc, asb, adb, alpha, 4);
    run_aggregate(hB, alpha, rowptr, csrsrc, b1, nullptr, hA, 4, 512, 7);

    // ---- layer 2: 512 -> 4x128 ----
    run_gemm(hA, wt2, hB, NN, 512, 512);
    node_alpha_kernel<<<nblocks_warps(NN * 4), 256>>>(hB, a2s, a2d, asb, adb, 4, 128);
    edge_softmax_kernel<<<nblocks_warps(NN * 4), 256>>>(rowptr, csrsrc, asb, adb, alpha, 4);
    run_aggregate(hB, alpha, rowptr, csrsrc, b2, nullptr, hA, 4, 512, 7);

    // ---- layer 3: 512 -> 4x64 ----
    run_gemm(hA, wt3, hB, NN, 256, 512);
    node_alpha_kernel<<<nblocks_warps(NN * 4), 256>>>(hB, a3s, a3d, asb, adb, 4, 64);
    edge_softmax_kernel<<<nblocks_warps(NN * 4), 256>>>(rowptr, csrsrc, asb, adb, alpha, 4);
    run_aggregate(hB, alpha, rowptr, csrsrc, b3, nullptr, hA, 4, 256, 6);

    // ---- layer 4: 256 -> 1x64, concat=False ----
    run_gemm(hA, wt4, hB, NN, 64, 256);
    node_alpha_kernel<<<nblocks_warps(NN * 1), 256>>>(hB, a4s, a4d, asb, adb, 1, 64);
    edge_softmax_kernel<<<nblocks_warps(NN * 1), 256>>>(rowptr, csrsrc, asb, adb, alpha, 1);
    run_aggregate(hB, alpha, rowptr, csrsrc, b4, out, nullptr, 1, 64, 6);

    (void)in_sizes; (void)n_in; (void)out_size;
}